// round 1
// baseline (speedup 1.0000x reference)
#include <cuda_runtime.h>
#include <math.h>

// ---------------- problem constants ----------------
#define DIMC   2048
#define NHEADS 2
#define HDIM   1024      // DIMC / NHEADS
#define BATCH  4
#define SEQ    2048
#define M1     (BATCH*SEQ)   // 8192 rows of x
#define QKVN   (3*DIMC)      // 6144

// ---------------- scratch (static device allocations) ----------------
__device__ float g_qkv[(size_t)M1 * QKVN];                       // 201 MB
__device__ float g_q  [(size_t)BATCH * NHEADS * SEQ * HDIM];     // 67 MB (roped Q)
__device__ float g_s  [(size_t)BATCH * NHEADS * SEQ * SEQ];      // 134 MB (scores/probs)
__device__ float g_vh [(size_t)M1 * DIMC];                       // 67 MB (attn out, BLD layout)
__device__ float g_ctab[SEQ * 512];
__device__ float g_stab[SEQ * 512];

// ---------------- RoPE tables (double precision, exact) ----------------
__global__ void rope_tab_kernel() {
    int idx = blockIdx.x * blockDim.x + threadIdx.x;   // l*512 + d
    int d = idx & 511;
    int l = idx >> 9;
    // inv[d] = exp(2d * (-ln(10000)/1024))
    double inv = exp((double)(2 * d) * (-9.210340371976184 / 1024.0));
    double th  = (double)l * inv;
    g_ctab[idx] = (float)cos(th);
    g_stab[idx] = (float)sin(th);
}

// ---------------- RoPE apply: QKV -> Qr (scratch), Kr,V -> d_out ----------------
__global__ void rope_apply_kernel(const float* __restrict__ qkv,
                                  float* __restrict__ qout,
                                  float* __restrict__ kout,
                                  float* __restrict__ vout) {
    int idx = blockIdx.x * blockDim.x + threadIdx.x;   // ((b*H+h)*L + l)*512 + d
    int d = idx & 511;
    int l = (idx >> 9) & (SEQ - 1);
    int h = (idx >> 20) & (NHEADS - 1);
    int b = idx >> 21;

    int ti = (l << 9) + d;
    float c = g_ctab[ti];
    float s = g_stab[ti];

    const float* row = qkv + (size_t)(b * SEQ + l) * QKVN;
    int off = h * HDIM + d;
    float q1 = row[off],            q2 = row[off + 512];
    float k1 = row[DIMC + off],     k2 = row[DIMC + off + 512];
    float v1 = row[2*DIMC + off],   v2 = row[2*DIMC + off + 512];

    size_t o = (size_t)((b * NHEADS + h) * SEQ + l) * HDIM + d;
    qout[o]       = q1 * c - q2 * s;
    qout[o + 512] = q1 * s + q2 * c;
    kout[o]       = k1 * c - k2 * s;
    kout[o + 512] = k1 * s + k2 * c;
    vout[o]       = v1;
    vout[o + 512] = v2;
}

// ---------------- row softmax over 2048 columns, 1 block/row ----------------
__global__ void softmax_kernel(float* __restrict__ S) {
    size_t row = blockIdx.x;
    float* p = S + row * (size_t)SEQ;
    int t = threadIdx.x;

    float v[8];
    float4 v0 = *(const float4*)(p + t * 8);
    float4 v1 = *(const float4*)(p + t * 8 + 4);
    v[0]=v0.x; v[1]=v0.y; v[2]=v0.z; v[3]=v0.w;
    v[4]=v1.x; v[5]=v1.y; v[6]=v1.z; v[7]=v1.w;

    float m = v[0];
    #pragma unroll
    for (int j = 1; j < 8; j++) m = fmaxf(m, v[j]);

    __shared__ float red[256];
    red[t] = m; __syncthreads();
    #pragma unroll
    for (int s = 128; s > 0; s >>= 1) {
        if (t < s) red[t] = fmaxf(red[t], red[t + s]);
        __syncthreads();
    }
    float mx = red[0];
    __syncthreads();

    float sum = 0.f;
    #pragma unroll
    for (int j = 0; j < 8; j++) { v[j] = expf(v[j] - mx); sum += v[j]; }
    red[t] = sum; __syncthreads();
    #pragma unroll
    for (int s = 128; s > 0; s >>= 1) {
        if (t < s) red[t] += red[t + s];
        __syncthreads();
    }
    float inv = 1.0f / red[0];

    #pragma unroll
    for (int j = 0; j < 8; j++) v[j] *= inv;
    *(float4*)(p + t * 8)     = make_float4(v[0], v[1], v[2], v[3]);
    *(float4*)(p + t * 8 + 4) = make_float4(v[4], v[5], v[6], v[7]);
}

// ---------------- generic tiled GEMM with FFMA2 micro-kernel ----------------
// C[M,N] = alpha * (A @ op(B)) (+ bias[col]) (+ mask[row,col])
//   BT=true : B is [N,K] row-major (compute A @ B^T)
//   BT=false: B is [K,N] row-major (compute A @ B)
// CAUSAL: 0 none; 1 fill tiles strictly above diagonal with -1e9 (scores);
//         2 limit K loop to (rowtile+1)*BM (PV, masked probs are exactly 0)
#define BMT 128
#define BNT 128
#define BKT 16
#define SPAD 4

template<bool BT, int CAUSAL>
__global__ void __launch_bounds__(256, 2) gemm_kernel(
    const float* __restrict__ A, const float* __restrict__ B,
    const float* __restrict__ bias, const float* __restrict__ Ms,
    float* __restrict__ C,
    int M, int N, int K, int lda, int ldb, int ldc, int ldm,
    long sA, long sB, long sCo, long sCi, int zdiv, float alpha)
{
    int bz = blockIdx.z;
    A += (size_t)bz * sA;
    B += (size_t)bz * sB;
    C += (size_t)(bz / zdiv) * sCo + (size_t)(bz % zdiv) * sCi;

    const int row0 = blockIdx.y * BMT;
    const int col0 = blockIdx.x * BNT;
    const int tid  = threadIdx.x;
    const int tx   = tid & 15;   // N direction
    const int ty   = tid >> 4;   // M direction

    if (CAUSAL == 1 && col0 > row0) {
        // strictly above diagonal: every (i,j) has j>i; reference rounds to -1e9 exactly
        float4 f = make_float4(-1e9f, -1e9f, -1e9f, -1e9f);
        #pragma unroll
        for (int i = 0; i < 8; i++) {
            float* cp = C + (size_t)(row0 + ty * 8 + i) * ldc + col0 + tx * 8;
            *(float4*)cp       = f;
            *(float4*)(cp + 4) = f;
        }
        return;
    }

    int Keff = K;
    if (CAUSAL == 2) Keff = min(K, row0 + BMT);

    __shared__ float As[BKT][BMT + SPAD];
    __shared__ float Bs[BKT][BNT + SPAD];

    unsigned long long acc[8][4];
    #pragma unroll
    for (int i = 0; i < 8; i++)
        #pragma unroll
        for (int p = 0; p < 4; p++) acc[i][p] = 0ULL;

    const int ar = tid >> 2;          // 0..63
    const int ak = (tid & 3) << 2;    // 0,4,8,12
    const int bc = (tid & 31) << 2;   // 0..124 (NN path)
    const int bk = tid >> 5;          // 0..7   (NN path)

    for (int k0 = 0; k0 < Keff; k0 += BKT) {
        // load A tile (transpose into As[k][m])
        #pragma unroll
        for (int p = 0; p < 2; p++) {
            float4 va = *(const float4*)(A + (size_t)(row0 + ar + p * 64) * lda + k0 + ak);
            As[ak + 0][ar + p * 64] = va.x;
            As[ak + 1][ar + p * 64] = va.y;
            As[ak + 2][ar + p * 64] = va.z;
            As[ak + 3][ar + p * 64] = va.w;
        }
        if (BT) {
            #pragma unroll
            for (int p = 0; p < 2; p++) {
                float4 vb = *(const float4*)(B + (size_t)(col0 + ar + p * 64) * ldb + k0 + ak);
                Bs[ak + 0][ar + p * 64] = vb.x;
                Bs[ak + 1][ar + p * 64] = vb.y;
                Bs[ak + 2][ar + p * 64] = vb.z;
                Bs[ak + 3][ar + p * 64] = vb.w;
            }
        } else {
            #pragma unroll
            for (int p = 0; p < 2; p++) {
                float4 vb = *(const float4*)(B + (size_t)(k0 + bk + p * 8) * ldb + col0 + bc);
                *(float4*)&Bs[bk + p * 8][bc] = vb;
            }
        }
        __syncthreads();

        #pragma unroll
        for (int kk = 0; kk < BKT; kk++) {
            float4 a0 = *(const float4*)&As[kk][ty * 8];
            float4 a1 = *(const float4*)&As[kk][ty * 8 + 4];
            ulonglong2 bb0 = *(const ulonglong2*)&Bs[kk][tx * 8];
            ulonglong2 bb1 = *(const ulonglong2*)&Bs[kk][tx * 8 + 4];
            unsigned long long bfr[4] = {bb0.x, bb0.y, bb1.x, bb1.y};
            float av[8] = {a0.x, a0.y, a0.z, a0.w, a1.x, a1.y, a1.z, a1.w};
            #pragma unroll
            for (int i = 0; i < 8; i++) {
                unsigned long long aa;
                unsigned int ai = __float_as_uint(av[i]);
                asm("mov.b64 %0, {%1, %2};" : "=l"(aa) : "r"(ai), "r"(ai));
                #pragma unroll
                for (int p = 0; p < 4; p++)
                    asm("fma.rn.f32x2 %0, %1, %2, %0;"
                        : "+l"(acc[i][p]) : "l"(aa), "l"(bfr[p]));
            }
        }
        __syncthreads();
    }

    // epilogue
    float bb[8];
    const bool hb = (bias != nullptr);
    if (hb) {
        float4 b0 = *(const float4*)(bias + col0 + tx * 8);
        float4 b1 = *(const float4*)(bias + col0 + tx * 8 + 4);
        bb[0]=b0.x; bb[1]=b0.y; bb[2]=b0.z; bb[3]=b0.w;
        bb[4]=b1.x; bb[5]=b1.y; bb[6]=b1.z; bb[7]=b1.w;
    }
    #pragma unroll
    for (int i = 0; i < 8; i++) {
        int row = row0 + ty * 8 + i;
        float o[8];
        #pragma unroll
        for (int p = 0; p < 4; p++) {
            unsigned int lo, hi;
            asm("mov.b64 {%0, %1}, %2;" : "=r"(lo), "=r"(hi) : "l"(acc[i][p]));
            o[2*p]     = __uint_as_float(lo) * alpha;
            o[2*p + 1] = __uint_as_float(hi) * alpha;
        }
        if (hb) {
            #pragma unroll
            for (int j = 0; j < 8; j++) o[j] += bb[j];
        }
        if (Ms) {
            const float* mp = Ms + (size_t)row * ldm + col0 + tx * 8;
            float4 m0 = *(const float4*)mp;
            float4 m1 = *(const float4*)(mp + 4);
            o[0]+=m0.x; o[1]+=m0.y; o[2]+=m0.z; o[3]+=m0.w;
            o[4]+=m1.x; o[5]+=m1.y; o[6]+=m1.z; o[7]+=m1.w;
        }
        float* cp = C + (size_t)row * ldc + col0 + tx * 8;
        *(float4*)cp       = make_float4(o[0], o[1], o[2], o[3]);
        *(float4*)(cp + 4) = make_float4(o[4], o[5], o[6], o[7]);
    }
}

// ---------------- launch ----------------
extern "C" void kernel_launch(void* const* d_in, const int* in_sizes, int n_in,
                              void* d_out, int out_size) {
    const float* x      = (const float*)d_in[0];
    const float* mask   = (const float*)d_in[1];
    const float* Wqkv_w = (const float*)d_in[2];
    const float* Wqkv_b = (const float*)d_in[3];
    const float* out_w  = (const float*)d_in[4];
    const float* out_b  = (const float*)d_in[5];

    float* out  = (float*)d_out;
    float* kout = out  + (size_t)M1 * DIMC;                      // (B,H,L,Dh)
    float* vout = kout + (size_t)BATCH * NHEADS * SEQ * HDIM;    // (B,H,L,Dh)

    float *qkv, *q, *S, *vh;
    cudaGetSymbolAddress((void**)&qkv, g_qkv);
    cudaGetSymbolAddress((void**)&q,   g_q);
    cudaGetSymbolAddress((void**)&S,   g_s);
    cudaGetSymbolAddress((void**)&vh,  g_vh);

    // 1) RoPE tables
    rope_tab_kernel<<<SEQ, 512>>>();

    // 2) QKV = x @ Wqkv_w^T + b      [8192 x 6144 x 2048]
    gemm_kernel<true, 0><<<dim3(QKVN / BNT, M1 / BMT, 1), 256>>>(
        x, Wqkv_w, Wqkv_b, nullptr, qkv,
        M1, QKVN, DIMC, DIMC, DIMC, QKVN, 0,
        0, 0, 0, 0, 1, 1.0f);

    // 3) RoPE: Qr -> scratch, Kr -> d_out, V -> d_out
    rope_apply_kernel<<<(BATCH * NHEADS * SEQ * 512) / 256, 256>>>(qkv, q, kout, vout);

    // 4) S = (1/32) * Qr @ Kr^T + mask   per (b,h): [2048 x 2048 x 1024], causal fill
    gemm_kernel<true, 1><<<dim3(SEQ / BNT, SEQ / BMT, BATCH * NHEADS), 256>>>(
        q, kout, nullptr, mask, S,
        SEQ, SEQ, HDIM, HDIM, HDIM, SEQ, SEQ,
        (long)SEQ * HDIM, (long)SEQ * HDIM, (long)SEQ * SEQ, 0, 1, 0.03125f);

    // 5) softmax rows (in place)
    softmax_kernel<<<BATCH * NHEADS * SEQ, 256>>>(S);

    // 6) VH = P @ V   per (b,h): [2048 x 1024 x 2048], causal k-limit; scatter to (B,L,D)
    gemm_kernel<false, 2><<<dim3(HDIM / BNT, SEQ / BMT, BATCH * NHEADS), 256>>>(
        S, vout, nullptr, nullptr, vh,
        SEQ, HDIM, SEQ, SEQ, HDIM, DIMC, 0,
        (long)SEQ * SEQ, (long)SEQ * HDIM, (long)SEQ * DIMC, (long)HDIM, NHEADS, 1.0f);

    // 7) out = VH @ out_w^T + out_b   [8192 x 2048 x 2048]
    gemm_kernel<true, 0><<<dim3(DIMC / BNT, M1 / BMT, 1), 256>>>(
        vh, out_w, out_b, nullptr, out,
        M1, DIMC, DIMC, DIMC, DIMC, DIMC, 0,
        0, 0, 0, 0, 1, 1.0f);
}

// round 3
// speedup vs baseline: 1.8160x; 1.8160x over previous
#include <cuda_runtime.h>
#include <cuda_bf16.h>
#include <math.h>
#include <stdint.h>

// ---------------- problem constants ----------------
#define DIMC   2048
#define NHEADS 2
#define HDIM   1024
#define BATCH  4
#define SEQ    2048
#define M1     (BATCH*SEQ)   // 8192
#define QKVN   (3*DIMC)      // 6144

__device__ __forceinline__ uint32_t smem_u32(const void* p) {
    uint32_t a;
    asm("{ .reg .u64 t; cvta.to.shared.u64 t, %1; cvt.u32.u64 %0, t; }" : "=r"(a) : "l"(p));
    return a;
}
__device__ __forceinline__ void split1(float v, __nv_bfloat16& h, __nv_bfloat16& l) {
    h = __float2bfloat16(v);
    l = __float2bfloat16(v - __bfloat162float(h));
}

#define CP_ASYNC16(dst, src) \
    asm volatile("cp.async.cg.shared.global [%0], [%1], 16;" :: "r"(dst), "l"(src) : "memory")
#define CP_COMMIT() asm volatile("cp.async.commit_group;" ::: "memory")
#define CP_WAIT1()  asm volatile("cp.async.wait_group 1;" ::: "memory")
#define CP_WAIT0()  asm volatile("cp.async.wait_group 0;" ::: "memory")

#define LDMATRIX_X4(r0, r1, r2, r3, addr) \
    asm volatile("ldmatrix.sync.aligned.m8n8.x4.shared.b16 {%0,%1,%2,%3}, [%4];" \
        : "=r"(r0), "=r"(r1), "=r"(r2), "=r"(r3) : "r"(addr))

#define MMA_BF16(c, a, b0, b1) \
    asm volatile("mma.sync.aligned.m16n8k16.row.col.f32.bf16.bf16.f32 " \
        "{%0,%1,%2,%3}, {%4,%5,%6,%7}, {%8,%9}, {%0,%1,%2,%3};" \
        : "+f"((c)[0]), "+f"((c)[1]), "+f"((c)[2]), "+f"((c)[3]) \
        : "r"((a)[0]), "r"((a)[1]), "r"((a)[2]), "r"((a)[3]), "r"(b0), "r"(b1))

// ---------------- scratch ----------------
__device__ float g_qkv[(size_t)M1 * QKVN];
__device__ float g_s  [(size_t)8 * SEQ * SEQ];
__device__ float g_ctab[SEQ * 512];
__device__ float g_stab[SEQ * 512];
__device__ __align__(128) __nv_bfloat16 g_xh[(size_t)M1*DIMC],  g_xl[(size_t)M1*DIMC];
__device__ __align__(128) __nv_bfloat16 g_wqh[(size_t)QKVN*DIMC], g_wql[(size_t)QKVN*DIMC];
__device__ __align__(128) __nv_bfloat16 g_owh[(size_t)DIMC*DIMC], g_owl[(size_t)DIMC*DIMC];
__device__ __align__(128) __nv_bfloat16 g_qh[(size_t)8*SEQ*HDIM], g_ql[(size_t)8*SEQ*HDIM];
__device__ __align__(128) __nv_bfloat16 g_kh[(size_t)8*SEQ*HDIM], g_kl[(size_t)8*SEQ*HDIM];
__device__ __align__(128) __nv_bfloat16 g_vth[(size_t)8*HDIM*SEQ], g_vtl[(size_t)8*HDIM*SEQ];
__device__ __align__(128) __nv_bfloat16 g_ph[(size_t)8*SEQ*SEQ],  g_pl[(size_t)8*SEQ*SEQ];
__device__ __align__(128) __nv_bfloat16 g_vhh[(size_t)M1*DIMC],  g_vhl[(size_t)M1*DIMC];

// ---------------- RoPE tables ----------------
__global__ void rope_tab_kernel() {
    int idx = blockIdx.x * blockDim.x + threadIdx.x;
    int d = idx & 511, l = idx >> 9;
    double inv = exp((double)(2 * d) * (-9.210340371976184 / 1024.0));
    double th  = (double)l * inv;
    g_ctab[idx] = (float)cos(th);
    g_stab[idx] = (float)sin(th);
}

// ---------------- fp32 -> bf16 hi/lo split ----------------
__global__ void conv_split(const float* __restrict__ in,
                           __nv_bfloat16* __restrict__ oh, __nv_bfloat16* __restrict__ ol) {
    int i = blockIdx.x * 256 + threadIdx.x;
    float4 v = ((const float4*)in)[i];
    union { __nv_bfloat16 b[4]; uint2 u; } H, L;
    split1(v.x, H.b[0], L.b[0]); split1(v.y, H.b[1], L.b[1]);
    split1(v.z, H.b[2], L.b[2]); split1(v.w, H.b[3], L.b[3]);
    ((uint2*)oh)[i] = H.u;
    ((uint2*)ol)[i] = L.u;
}

// ---------------- RoPE apply ----------------
__global__ void rope_apply(const float* __restrict__ qkv,
                           __nv_bfloat16* __restrict__ qh, __nv_bfloat16* __restrict__ ql,
                           __nv_bfloat16* __restrict__ kh, __nv_bfloat16* __restrict__ kl,
                           float* __restrict__ kout, float* __restrict__ vout) {
    int idx = blockIdx.x * blockDim.x + threadIdx.x;
    int d = idx & 511;
    int l = (idx >> 9) & (SEQ - 1);
    int h = (idx >> 20) & 1;
    int b = idx >> 21;
    int ti = (l << 9) + d;
    float c = g_ctab[ti], s = g_stab[ti];
    const float* row = qkv + (size_t)(b * SEQ + l) * QKVN;
    int off = h * HDIM + d;
    float q1 = row[off],          q2 = row[off + 512];
    float k1 = row[DIMC + off],   k2 = row[DIMC + off + 512];
    float v1 = row[2*DIMC + off], v2 = row[2*DIMC + off + 512];
    size_t o = (size_t)((b * NHEADS + h) * SEQ + l) * HDIM + d;
    float rq1 = q1*c - q2*s, rq2 = q1*s + q2*c;
    float rk1 = k1*c - k2*s, rk2 = k1*s + k2*c;
    split1(rq1, qh[o],       ql[o]);
    split1(rq2, qh[o + 512], ql[o + 512]);
    split1(rk1, kh[o],       kl[o]);
    split1(rk2, kh[o + 512], kl[o + 512]);
    kout[o] = rk1; kout[o + 512] = rk2;
    vout[o] = v1;  vout[o + 512] = v2;
}

// ---------------- V transpose + split: qkv(v) -> Vt[b,h,d,l] hi/lo ----------------
__global__ void vt_kernel(const float* __restrict__ qkv,
                          __nv_bfloat16* __restrict__ vth, __nv_bfloat16* __restrict__ vtl) {
    __shared__ float tile[32][33];
    int z = blockIdx.z;
    int b = z >> 1, h = z & 1;
    int l0 = blockIdx.x * 32, d0 = blockIdx.y * 32;
    int tx = threadIdx.x, ty = threadIdx.y;
    #pragma unroll
    for (int j = 0; j < 32; j += 8) {
        int l = l0 + ty + j, d = d0 + tx;
        tile[ty + j][tx] = qkv[(size_t)(b * SEQ + l) * QKVN + 2*DIMC + h*HDIM + d];
    }
    __syncthreads();
    #pragma unroll
    for (int j = 0; j < 32; j += 8) {
        int d = d0 + ty + j, l = l0 + tx;
        float v = tile[tx][ty + j];
        size_t o = ((size_t)z * HDIM + d) * SEQ + l;
        split1(v, vth[o], vtl[o]);
    }
}

// ---------------- softmax + split to bf16 hi/lo ----------------
__global__ void softmax_split(const float* __restrict__ S,
                              __nv_bfloat16* __restrict__ Ph, __nv_bfloat16* __restrict__ Pl) {
    size_t row = blockIdx.x;
    const float* p = S + row * (size_t)SEQ;
    int t = threadIdx.x;
    float v[8];
    float4 v0 = *(const float4*)(p + t * 8);
    float4 v1 = *(const float4*)(p + t * 8 + 4);
    v[0]=v0.x; v[1]=v0.y; v[2]=v0.z; v[3]=v0.w;
    v[4]=v1.x; v[5]=v1.y; v[6]=v1.z; v[7]=v1.w;
    float m = v[0];
    #pragma unroll
    for (int j = 1; j < 8; j++) m = fmaxf(m, v[j]);
    __shared__ float red[256];
    red[t] = m; __syncthreads();
    #pragma unroll
    for (int s = 128; s > 0; s >>= 1) { if (t < s) red[t] = fmaxf(red[t], red[t + s]); __syncthreads(); }
    float mx = red[0]; __syncthreads();
    float sum = 0.f;
    #pragma unroll
    for (int j = 0; j < 8; j++) { v[j] = expf(v[j] - mx); sum += v[j]; }
    red[t] = sum; __syncthreads();
    #pragma unroll
    for (int s = 128; s > 0; s >>= 1) { if (t < s) red[t] += red[t + s]; __syncthreads(); }
    float inv = 1.0f / red[0];
    union { __nv_bfloat16 b[8]; uint4 u; } H, L;
    #pragma unroll
    for (int j = 0; j < 8; j++) { v[j] *= inv; split1(v[j], H.b[j], L.b[j]); }
    *(uint4*)(Ph + row * SEQ + t * 8) = H.u;
    *(uint4*)(Pl + row * SEQ + t * 8) = L.u;
}

// ---------------- warp-MMA split-bf16 GEMM ----------------
// C = alpha*(A@B^T) (+bias) (+mask). A=[M,K] K-major hi/lo, B=[N,K] K-major hi/lo.
// Block 128x128x32, 8 warps (4x2), warp tile 32x64, m16n8k16 bf16 MMA, 3-stage cp.async.
// CAUSAL: 0 none; 1 fill above-diag tiles with -1e9; 2 K-limit to row0+128.
// EPI: 0 -> fp32 C0; 1 -> split to bf16 C0(hi)/C1(lo).
#define KPAD   40                  // padded row stride in bf16 (80 B)
#define MATB   (128 * KPAD * 2)    // 10240 B per matrix tile
#define STGB   (4 * MATB)          // 40960 B per stage
#define NSTG   3
#define SMEM_MMA (NSTG * STGB)

__device__ __forceinline__ void load_stage_async(uint32_t sbase,
    const __nv_bfloat16* Ah, const __nv_bfloat16* Al,
    const __nv_bfloat16* Bh, const __nv_bfloat16* Bl,
    int lda, int ldb, int row0, int col0, int k0)
{
    const int t = threadIdx.x;
    const __nv_bfloat16* srcs[4] = {Ah, Al, Bh, Bl};
    #pragma unroll
    for (int i = 0; i < 8; i++) {
        int s = t + i * 256;
        int m   = s >> 9;           // matrix 0..3
        int idx = s & 511;
        int row = idx >> 2;
        int c16 = idx & 3;          // 16B segment within 64B row
        int ld  = (m < 2) ? lda : ldb;
        int r0  = (m < 2) ? row0 : col0;
        const __nv_bfloat16* src = srcs[m] + (size_t)(r0 + row) * ld + k0 + c16 * 8;
        uint32_t dst = sbase + m * MATB + row * (KPAD * 2) + c16 * 16;
        CP_ASYNC16(dst, src);
    }
}

template<int CAUSAL, int EPI>
__global__ void __launch_bounds__(256, 1) gemm_mma(
    const __nv_bfloat16* __restrict__ Ah, const __nv_bfloat16* __restrict__ Al,
    const __nv_bfloat16* __restrict__ Bh, const __nv_bfloat16* __restrict__ Bl,
    const float* __restrict__ bias, const float* __restrict__ Ms,
    void* __restrict__ C0, void* __restrict__ C1,
    int K, int lda, int ldb, int ldc, int ldm,
    long sA, long sB, long sCo, long sCi, int zdiv, float alpha)
{
    extern __shared__ char smem[];
    const int tid = threadIdx.x;
    const int wid = tid >> 5;
    const int lid = tid & 31;
    const int row0 = blockIdx.y * 128;
    const int col0 = blockIdx.x * 128;
    const int bz = blockIdx.z;

    const size_t zoffC = (size_t)(bz / zdiv) * sCo + (size_t)(bz % zdiv) * sCi;
    Ah += (size_t)bz * sA; Al += (size_t)bz * sA;
    Bh += (size_t)bz * sB; Bl += (size_t)bz * sB;

    if (CAUSAL == 1 && col0 > row0) {
        float* C = (float*)C0 + zoffC;
        float4 f = make_float4(-1e9f, -1e9f, -1e9f, -1e9f);
        #pragma unroll
        for (int i = 0; i < 16; i++) {
            int g = tid + i * 256;
            int r = g >> 5, c4 = (g & 31) << 2;
            *(float4*)(C + (size_t)(row0 + r) * ldc + col0 + c4) = f;
        }
        return;
    }

    int Keff = (CAUSAL == 2) ? min(K, row0 + 128) : K;
    const int nc = Keff >> 5;                 // 32-wide K chunks

    const uint32_t sb = smem_u32(smem);
    const int wm = (wid & 3) * 32;            // warp row offset in tile
    const int wn = (wid >> 2) * 64;           // warp col offset in tile

    float acc[2][8][4];
    #pragma unroll
    for (int mt = 0; mt < 2; mt++)
        #pragma unroll
        for (int nt = 0; nt < 8; nt++)
            #pragma unroll
            for (int r = 0; r < 4; r++) acc[mt][nt][r] = 0.f;

    load_stage_async(sb, Ah, Al, Bh, Bl, lda, ldb, row0, col0, 0);
    CP_COMMIT();
    if (nc > 1) load_stage_async(sb + STGB, Ah, Al, Bh, Bl, lda, ldb, row0, col0, 32);
    CP_COMMIT();

    // per-lane ldmatrix address pieces
    const int lrow = lid & 15;                // row within 16-row group
    const int lcol = (lid >> 4) << 3;         // 0 or 8 (k offset)

    for (int c = 0; c < nc; c++) {
        if (c + 1 < nc) { CP_WAIT1(); } else { CP_WAIT0(); }
        __syncthreads();
        if (c + 2 < nc) {
            load_stage_async(sb + ((c + 2) % NSTG) * STGB, Ah, Al, Bh, Bl,
                             lda, ldb, row0, col0, (c + 2) << 5);
            CP_COMMIT();
        }

        uint32_t stg = sb + (c % NSTG) * STGB;
        #pragma unroll
        for (int kk = 0; kk < 32; kk += 16) {
            uint32_t aH[2][4], aL[2][4], bH[4][4], bL[4][4];
            #pragma unroll
            for (int mt = 0; mt < 2; mt++) {
                uint32_t ra = stg + ((wm + mt * 16 + lrow) * KPAD + kk + lcol) * 2;
                LDMATRIX_X4(aH[mt][0], aH[mt][1], aH[mt][2], aH[mt][3], ra);
                LDMATRIX_X4(aL[mt][0], aL[mt][1], aL[mt][2], aL[mt][3], ra + MATB);
            }
            #pragma unroll
            for (int g = 0; g < 4; g++) {
                uint32_t rb = stg + 2 * MATB + ((wn + g * 16 + lrow) * KPAD + kk + lcol) * 2;
                LDMATRIX_X4(bH[g][0], bH[g][1], bH[g][2], bH[g][3], rb);
                LDMATRIX_X4(bL[g][0], bL[g][1], bL[g][2], bL[g][3], rb + MATB);
            }
            #pragma unroll
            for (int mt = 0; mt < 2; mt++)
                #pragma unroll
                for (int nt = 0; nt < 8; nt++) {
                    int g = nt >> 1, o = nt & 1;
                    MMA_BF16(acc[mt][nt], aH[mt], bH[g][o],     bH[g][o + 2]);
                    MMA_BF16(acc[mt][nt], aH[mt], bL[g][o],     bL[g][o + 2]);
                    MMA_BF16(acc[mt][nt], aL[mt], bH[g][o],     bH[g][o + 2]);
                }
        }
        __syncthreads();
    }

    // ---------------- epilogue ----------------
    #pragma unroll
    for (int mt = 0; mt < 2; mt++) {
        #pragma unroll
        for (int nt = 0; nt < 8; nt++) {
            int gr0 = row0 + wm + mt * 16 + (lid >> 2);
            int gc  = col0 + wn + nt * 8 + (lid & 3) * 2;
            #pragma unroll
            for (int half = 0; half < 2; half++) {
                int gr = gr0 + half * 8;
                float v0 = acc[mt][nt][2 * half]     * alpha;
                float v1 = acc[mt][nt][2 * half + 1] * alpha;
                if (bias) { v0 += bias[gc]; v1 += bias[gc + 1]; }
                if (CAUSAL == 1) {
                    const float* mp = Ms + (size_t)gr * ldm + gc;
                    v0 += mp[0]; v1 += mp[1];
                }
                if (EPI == 0) {
                    float* C = (float*)C0 + zoffC + (size_t)gr * ldc + gc;
                    float2 w = make_float2(v0, v1);
                    *(float2*)C = w;
                } else {
                    __nv_bfloat16* Ch = (__nv_bfloat16*)C0 + zoffC + (size_t)gr * ldc + gc;
                    __nv_bfloat16* Cl = (__nv_bfloat16*)C1 + zoffC + (size_t)gr * ldc + gc;
                    union { __nv_bfloat16 b[2]; uint32_t u; } H, L;
                    split1(v0, H.b[0], L.b[0]);
                    split1(v1, H.b[1], L.b[1]);
                    *(uint32_t*)Ch = H.u;
                    *(uint32_t*)Cl = L.u;
                }
            }
        }
    }
}

// ---------------- launch ----------------
extern "C" void kernel_launch(void* const* d_in, const int* in_sizes, int n_in,
                              void* d_out, int out_size) {
    const float* x      = (const float*)d_in[0];
    const float* mask   = (const float*)d_in[1];
    const float* Wqkv_w = (const float*)d_in[2];
    const float* Wqkv_b = (const float*)d_in[3];
    const float* out_w  = (const float*)d_in[4];
    const float* out_b  = (const float*)d_in[5];

    float* out  = (float*)d_out;
    float* kout = out  + (size_t)M1 * DIMC;
    float* vout = kout + (size_t)8 * SEQ * HDIM;

    float *qkv, *S;
    __nv_bfloat16 *xh,*xl,*wqh,*wql,*owh,*owl,*qh,*ql,*kh,*kl,*vth,*vtl,*ph,*pl,*vhh,*vhl;
    cudaGetSymbolAddress((void**)&qkv, g_qkv);
    cudaGetSymbolAddress((void**)&S,   g_s);
    cudaGetSymbolAddress((void**)&xh,  g_xh);  cudaGetSymbolAddress((void**)&xl,  g_xl);
    cudaGetSymbolAddress((void**)&wqh, g_wqh); cudaGetSymbolAddress((void**)&wql, g_wql);
    cudaGetSymbolAddress((void**)&owh, g_owh); cudaGetSymbolAddress((void**)&owl, g_owl);
    cudaGetSymbolAddress((void**)&qh,  g_qh);  cudaGetSymbolAddress((void**)&ql,  g_ql);
    cudaGetSymbolAddress((void**)&kh,  g_kh);  cudaGetSymbolAddress((void**)&kl,  g_kl);
    cudaGetSymbolAddress((void**)&vth, g_vth); cudaGetSymbolAddress((void**)&vtl, g_vtl);
    cudaGetSymbolAddress((void**)&ph,  g_ph);  cudaGetSymbolAddress((void**)&pl,  g_pl);
    cudaGetSymbolAddress((void**)&vhh, g_vhh); cudaGetSymbolAddress((void**)&vhl, g_vhl);

    cudaFuncSetAttribute(gemm_mma<0,0>, cudaFuncAttributeMaxDynamicSharedMemorySize, SMEM_MMA);
    cudaFuncSetAttribute(gemm_mma<1,0>, cudaFuncAttributeMaxDynamicSharedMemorySize, SMEM_MMA);
    cudaFuncSetAttribute(gemm_mma<2,1>, cudaFuncAttributeMaxDynamicSharedMemorySize, SMEM_MMA);

    // 1) RoPE tables
    rope_tab_kernel<<<SEQ, 512>>>();

    // 2) split inputs to bf16 hi/lo
    conv_split<<<(int)((size_t)M1*DIMC/1024),  256>>>(x, xh, xl);
    conv_split<<<(int)((size_t)QKVN*DIMC/1024),256>>>(Wqkv_w, wqh, wql);
    conv_split<<<(int)((size_t)DIMC*DIMC/1024),256>>>(out_w, owh, owl);

    // 3) QKV = x @ Wqkv^T + b   [8192 x 6144 x 2048]
    gemm_mma<0,0><<<dim3(QKVN/128, M1/128, 1), 256, SMEM_MMA>>>(
        xh, xl, wqh, wql, Wqkv_b, nullptr, qkv, nullptr,
        DIMC, DIMC, DIMC, QKVN, 0, 0, 0, 0, 0, 1, 1.0f);

    // 4) RoPE: roped q/k hi-lo, k/v fp32 -> d_out
    rope_apply<<<(8 * SEQ * 512) / 256, 256>>>(qkv, qh, ql, kh, kl, kout, vout);

    // 5) V transpose + split: Vt[b,h,d,l]
    vt_kernel<<<dim3(SEQ/32, HDIM/32, 8), dim3(32, 8)>>>(qkv, vth, vtl);

    // 6) S = (1/32) q @ k^T + mask  per head, causal fill
    gemm_mma<1,0><<<dim3(SEQ/128, SEQ/128, 8), 256, SMEM_MMA>>>(
        qh, ql, kh, kl, nullptr, mask, S, nullptr,
        HDIM, HDIM, HDIM, SEQ, SEQ,
        (long)SEQ*HDIM, (long)SEQ*HDIM, (long)SEQ*SEQ, 0, 1, 0.03125f);

    // 7) softmax + split P to bf16 hi/lo
    softmax_split<<<8 * SEQ, 256>>>(S, ph, pl);

    // 8) VH = P @ V (via Vt), causal K-limit; split output scattered to (B,L,D)
    gemm_mma<2,1><<<dim3(HDIM/128, SEQ/128, 8), 256, SMEM_MMA>>>(
        ph, pl, vth, vtl, nullptr, nullptr, vhh, vhl,
        SEQ, SEQ, SEQ, DIMC, 0,
        (long)SEQ*SEQ, (long)HDIM*SEQ, (long)SEQ*DIMC, (long)HDIM, NHEADS, 1.0f);

    // 9) out = VH @ out_w^T + out_b  [8192 x 2048 x 2048]
    gemm_mma<0,0><<<dim3(DIMC/128, M1/128, 1), 256, SMEM_MMA>>>(
        vhh, vhl, owh, owl, out_b, nullptr, out, nullptr,
        DIMC, DIMC, DIMC, DIMC, 0, 0, 0, 0, 0, 1, 1.0f);
}